// round 2
// baseline (speedup 1.0000x reference)
#include <cuda_runtime.h>

#define NN 50000
#define NE 800000
#define F  128

// ---------------- device scratch (no allocations allowed) -------------------
__device__ int   g_deg_out_i[NN];
__device__ int   g_deg_in_i[NN];
__device__ int   g_row_start[NN];
__device__ int   g_cursor[NN];
__device__ float g_scale_out[NN];     // rsqrt(max(deg_out,1))
__device__ int   g_perm_src[NE];      // src indices grouped by dst

// ---------------------------------------------------------------------------
// 1) zero degree/histogram arrays
// ---------------------------------------------------------------------------
__global__ void zero_kernel() {
    int i = blockIdx.x * blockDim.x + threadIdx.x;
    if (i < NN) { g_deg_out_i[i] = 0; g_deg_in_i[i] = 0; }
}

// ---------------------------------------------------------------------------
// 2) degree histograms (int atomics, 1.6M ops)
// ---------------------------------------------------------------------------
__global__ void deg_kernel(const int* __restrict__ src, const int* __restrict__ dst) {
    int e = blockIdx.x * blockDim.x + threadIdx.x;
    if (e < NE) {
        atomicAdd(&g_deg_out_i[src[e]], 1);
        atomicAdd(&g_deg_in_i[dst[e]], 1);
    }
}

// ---------------------------------------------------------------------------
// 3) single-block scan: row_start = exclusive_prefix(deg_in),
//    cursor = row_start copy, scale_out = rsqrt(max(deg_out,1))
// ---------------------------------------------------------------------------
#define SCAN_T 1024
#define CHUNK  ((NN + SCAN_T - 1) / SCAN_T)   // 49

__global__ void __launch_bounds__(SCAN_T)
scan_kernel() {
    __shared__ int part[SCAN_T];
    int t = threadIdx.x;
    int base = t * CHUNK;

    int s = 0;
    for (int i = 0; i < CHUNK; i++) {
        int idx = base + i;
        if (idx < NN) s += g_deg_in_i[idx];
    }
    part[t] = s;
    __syncthreads();

    // Hillis-Steele inclusive scan over 1024 partials
    for (int off = 1; off < SCAN_T; off <<= 1) {
        int v = (t >= off) ? part[t - off] : 0;
        __syncthreads();
        part[t] += v;
        __syncthreads();
    }
    int running = part[t] - s;   // exclusive offset for this chunk

    for (int i = 0; i < CHUNK; i++) {
        int idx = base + i;
        if (idx < NN) {
            g_row_start[idx] = running;
            g_cursor[idx]    = running;
            running += g_deg_in_i[idx];
            g_scale_out[idx] = rsqrtf(fmaxf((float)g_deg_out_i[idx], 1.0f));
        }
    }
}

// ---------------------------------------------------------------------------
// 4) counting-sort scatter: group src indices by dst
// ---------------------------------------------------------------------------
__global__ void scatter_kernel(const int* __restrict__ src, const int* __restrict__ dst) {
    int e = blockIdx.x * blockDim.x + threadIdx.x;
    if (e < NE) {
        int d = dst[e];
        int pos = atomicAdd(&g_cursor[d], 1);
        g_perm_src[pos] = src[e];
    }
}

// ---------------------------------------------------------------------------
// 5) fused gather-aggregate + norm + GEMM + bias
//    Block: 256 thr / 8 warps, 32 nodes per block (4 per warp).
//    Aggregate each node's in-edges into registers (left norm folded into
//    gather, right norm folded into accumulator), stage rows in smem, then
//    GEMM against W (smem-resident) with 4-row W amortization.
// ---------------------------------------------------------------------------
__global__ void __launch_bounds__(256, 2)
fused_kernel(const float* __restrict__ x, const float* __restrict__ weight,
             const float* __restrict__ bias, float* __restrict__ out) {
    extern __shared__ float sm[];
    float* Wsh = sm;            // 128*128 = 64KB
    float* Hsh = sm + F * F;    // 32*128  = 16KB

    int tid  = threadIdx.x;
    int warp = tid >> 5;
    int lane = tid & 31;
    int row0 = blockIdx.x * 32;

    // stage W (coalesced float4); loads issue early, overlap with gather
    for (int i = tid; i < F * F / 4; i += 256)
        reinterpret_cast<float4*>(Wsh)[i] = reinterpret_cast<const float4*>(weight)[i];

    const float4* x4 = reinterpret_cast<const float4*>(x);

    // ---- aggregation: 4 nodes per warp ----
#pragma unroll
    for (int r = 0; r < 4; r++) {
        int v = row0 + warp * 4 + r;
        float4 acc = make_float4(0.f, 0.f, 0.f, 0.f);
        if (v < NN) {
            int start = g_row_start[v];
            int len   = g_deg_in_i[v];
            const int* ps = g_perm_src + start;
            int i = 0;
            for (; i + 2 <= len; i += 2) {
                int s0 = ps[i], s1 = ps[i + 1];
                float sc0 = g_scale_out[s0];
                float sc1 = g_scale_out[s1];
                float4 a = x4[(size_t)s0 * 32 + lane];
                float4 b = x4[(size_t)s1 * 32 + lane];
                acc.x += sc0 * a.x; acc.y += sc0 * a.y;
                acc.z += sc0 * a.z; acc.w += sc0 * a.w;
                acc.x += sc1 * b.x; acc.y += sc1 * b.y;
                acc.z += sc1 * b.z; acc.w += sc1 * b.w;
            }
            if (i < len) {
                int s0 = ps[i];
                float sc0 = g_scale_out[s0];
                float4 a = x4[(size_t)s0 * 32 + lane];
                acc.x += sc0 * a.x; acc.y += sc0 * a.y;
                acc.z += sc0 * a.z; acc.w += sc0 * a.w;
            }
            // right norm folded here (row scaling commutes with @W)
            float inv = rsqrtf(fmaxf((float)len, 1.0f));
            acc.x *= inv; acc.y *= inv; acc.z *= inv; acc.w *= inv;
        }
        reinterpret_cast<float4*>(Hsh + (warp * 4 + r) * F)[lane] = acc;
    }

    __syncthreads();   // W staged + all H rows visible

    // ---- GEMM: warp computes its 4 rows, lane owns cols [4*lane..4*lane+3] ----
    int r0 = warp * 4;
    float4 accO[4];
#pragma unroll
    for (int r = 0; r < 4; r++) accO[r] = make_float4(0.f, 0.f, 0.f, 0.f);

#pragma unroll 4
    for (int k = 0; k < F; k++) {
        float4 wv = reinterpret_cast<float4*>(Wsh)[k * 32 + lane];
#pragma unroll
        for (int r = 0; r < 4; r++) {
            float hv = Hsh[(r0 + r) * F + k];   // warp broadcast
            accO[r].x += hv * wv.x;
            accO[r].y += hv * wv.y;
            accO[r].z += hv * wv.z;
            accO[r].w += hv * wv.w;
        }
    }

    float4 bv = reinterpret_cast<const float4*>(bias)[lane];
#pragma unroll
    for (int r = 0; r < 4; r++) {
        int row = row0 + r0 + r;
        if (row < NN) {
            float4 o;
            o.x = accO[r].x + bv.x;
            o.y = accO[r].y + bv.y;
            o.z = accO[r].z + bv.z;
            o.w = accO[r].w + bv.w;
            reinterpret_cast<float4*>(out + (size_t)row * F)[lane] = o;
        }
    }
}

// ---------------------------------------------------------------------------
extern "C" void kernel_launch(void* const* d_in, const int* in_sizes, int n_in,
                              void* d_out, int out_size) {
    const float* x      = (const float*)d_in[0];
    const int*   src    = (const int*)d_in[1];
    const int*   dst    = (const int*)d_in[2];
    const float* weight = (const float*)d_in[3];
    const float* bias   = (const float*)d_in[4];
    float*       out    = (float*)d_out;

    zero_kernel<<<(NN + 255) / 256, 256>>>();
    deg_kernel<<<(NE + 255) / 256, 256>>>(src, dst);
    scan_kernel<<<1, SCAN_T>>>();
    scatter_kernel<<<(NE + 255) / 256, 256>>>(src, dst);

    int smem = (F * F + 32 * F) * (int)sizeof(float);  // 81920 B
    cudaFuncSetAttribute(fused_kernel, cudaFuncAttributeMaxDynamicSharedMemorySize, smem);
    fused_kernel<<<(NN + 31) / 32, 256, smem>>>(x, weight, bias, out);
}